// round 1
// baseline (speedup 1.0000x reference)
#include <cuda_runtime.h>
#include <math.h>

#define NPOS 16384          // H*W
#define NB   16             // batch
#define NCH  128            // C == hidden
#define NCHUNK 32           // k-softmax / context n-chunks (512 each)

// ---------------- device scratch (allocation-free rule: __device__ globals) ----
__device__ float g_q[NB * NCH * NPOS];           // softmaxed*scale q  [b][h*32+d][n]
__device__ float g_k[NB * NCH * NPOS];           // raw k             [b][h*32+d][n]
__device__ float g_v[NB * NCH * NPOS];           // raw v             [b][h*32+e][n]
__device__ float g_part[NB * 4 * NCHUNK * 1056]; // per (b,h,chunk): 1024 ctx + 32 sumexp
__device__ float g_W2T[NB * NCH * NCH];          // fused weight, [b][ch=h*32+d][c]

// =============================================================================
// K1: qkv = w_qkv @ x  (384 out-ch x 128 positions per block), fused q-softmax
// smem: xs[128][128] | ws[128][68] | qb[128][132]   = 167,936 B
// =============================================================================
__global__ __launch_bounds__(256, 1)
void k_qkv(const float* __restrict__ x, const float* __restrict__ w_qkv)
{
    extern __shared__ float sm[];
    float* xs = sm;               // [c][p]   stride 128
    float* ws = sm + 16384;       // [c][o]   stride 68 (padded)
    float* qb = ws + 8704;        // [ch][p]  stride 132 (padded)

    const int b   = blockIdx.x >> 7;
    const int n0  = (blockIdx.x & 127) << 7;
    const int tid = threadIdx.x;

    const float* xb = x + (size_t)b * NCH * NPOS + n0;

    // load x tile (coalesced float4)
#pragma unroll
    for (int i = 0; i < 16; i++) {
        int lin = tid + i * 256;          // 4096 float4
        int c = lin >> 5, pv = lin & 31;
        ((float4*)xs)[c * 32 + pv] = ((const float4*)(xb + (size_t)c * NPOS))[pv];
    }
    __syncthreads();

    const int to = tid >> 4, tp = tid & 15;
    const int o0 = to * 4,   p0 = tp * 8;

    for (int chunk = 0; chunk < 6; chunk++) {
        // load w chunk transposed: ws[c][o], o in [chunk*64, +64)
#pragma unroll
        for (int i = 0; i < 32; i++) {
            int lin = tid + i * 256;      // 8192
            int o = lin >> 7, c = lin & 127;
            ws[c * 68 + o] = w_qkv[(chunk * 64 + o) * NCH + c];
        }
        __syncthreads();

        float acc[4][8];
#pragma unroll
        for (int i = 0; i < 4; i++)
#pragma unroll
            for (int j = 0; j < 8; j++) acc[i][j] = 0.f;

#pragma unroll 4
        for (int c = 0; c < 128; c++) {
            const float4 wv = *(const float4*)&ws[c * 68 + o0];
            const float4 a0 = *(const float4*)&xs[c * 128 + p0];
            const float4 a1 = *(const float4*)&xs[c * 128 + p0 + 4];
            const float w4[4] = {wv.x, wv.y, wv.z, wv.w};
            const float xv[8] = {a0.x, a0.y, a0.z, a0.w, a1.x, a1.y, a1.z, a1.w};
#pragma unroll
            for (int i = 0; i < 4; i++)
#pragma unroll
                for (int j = 0; j < 8; j++)
                    acc[i][j] = fmaf(w4[i], xv[j], acc[i][j]);
        }

        const int och = chunk * 64 + o0;  // global output channel base (0..383)
        if (chunk < 2) {                  // q -> smem for softmax
#pragma unroll
            for (int i = 0; i < 4; i++) {
                float* r = &qb[(och + i) * 132 + p0];
                *(float4*)(r)     = make_float4(acc[i][0], acc[i][1], acc[i][2], acc[i][3]);
                *(float4*)(r + 4) = make_float4(acc[i][4], acc[i][5], acc[i][6], acc[i][7]);
            }
        } else {
            float* gdst = (chunk < 4) ? g_k : g_v;
            const int ch = och - ((chunk < 4) ? 128 : 256);
            float* dst = gdst + ((size_t)b * NCH + ch) * NPOS + n0 + p0;
#pragma unroll
            for (int i = 0; i < 4; i++) {
                *(float4*)(dst + (size_t)i * NPOS)     = make_float4(acc[i][0], acc[i][1], acc[i][2], acc[i][3]);
                *(float4*)(dst + (size_t)i * NPOS + 4) = make_float4(acc[i][4], acc[i][5], acc[i][6], acc[i][7]);
            }
        }
        __syncthreads();
    }

    // q softmax over d (32) per (h, p), then * DIM_HEAD^-0.5
    const float scale = 0.17677669529663687f; // 32^-0.5
#pragma unroll
    for (int it = 0; it < 2; it++) {
        int item = tid + it * 256;        // 512 = 4 heads * 128 p
        int h = item >> 7, p = item & 127;
        float m = -1e30f;
#pragma unroll
        for (int d = 0; d < 32; d++) m = fmaxf(m, qb[(h * 32 + d) * 132 + p]);
        float s = 0.f;
#pragma unroll
        for (int d = 0; d < 32; d++) {
            float e = __expf(qb[(h * 32 + d) * 132 + p] - m);
            qb[(h * 32 + d) * 132 + p] = e;
            s += e;
        }
        const float inv = scale / s;
        float* dst = g_q + ((size_t)b * NCH + h * 32) * NPOS + n0 + p;
#pragma unroll
        for (int d = 0; d < 32; d++)
            dst[(size_t)d * NPOS] = qb[(h * 32 + d) * 132 + p] * inv;
    }
}

// =============================================================================
// K2a: per (b,h,chunk of 512 n): partial ctx[d][e] = sum exp(k[d,n]) v[e,n]
//      plus partial sumexp per d.  smem: ekT[512][36] | vT[512][36] = 147,456 B
// =============================================================================
__global__ __launch_bounds__(256, 1)
void k_ctx_part()
{
    extern __shared__ float sm[];
    float* ekT = sm;            // [nn][d] stride 36
    float* vT  = sm + 18432;

    const int chunk = blockIdx.x & 31;
    const int bh    = blockIdx.x >> 5;   // b*4 + h
    const int tid   = threadIdx.x;
    const size_t base = (size_t)bh * 32 * NPOS + (size_t)chunk * 512;

    for (int i = 0; i < 64; i++) {
        int lin = tid + i * 256;         // 16384 = 32 d x 512 nn
        int d = lin >> 9, nn = lin & 511;
        ekT[nn * 36 + d] = __expf(g_k[base + (size_t)d * NPOS + nn]);
        vT [nn * 36 + d] =        g_v[base + (size_t)d * NPOS + nn];
    }
    __syncthreads();

    const int g  = tid >> 6;             // 4 groups, each owns 128 nn
    const int t  = tid & 63;
    const int td = t >> 3, te = t & 7;
    const int d0 = td * 4, e0 = te * 4;

    float acc[4][4];
#pragma unroll
    for (int i = 0; i < 4; i++)
#pragma unroll
        for (int j = 0; j < 4; j++) acc[i][j] = 0.f;
    float sa0 = 0.f, sa1 = 0.f, sa2 = 0.f, sa3 = 0.f;

#pragma unroll 4
    for (int i = 0; i < 128; i++) {
        int nn = g * 128 + i;
        const float4 a  = *(const float4*)&ekT[nn * 36 + d0];
        const float4 bv = *(const float4*)&vT [nn * 36 + e0];
        const float av[4] = {a.x, a.y, a.z, a.w};
        const float bb[4] = {bv.x, bv.y, bv.z, bv.w};
#pragma unroll
        for (int ii = 0; ii < 4; ii++)
#pragma unroll
            for (int jj = 0; jj < 4; jj++)
                acc[ii][jj] = fmaf(av[ii], bb[jj], acc[ii][jj]);
        if (te == 0) { sa0 += a.x; sa1 += a.y; sa2 += a.z; sa3 += a.w; }
    }
    __syncthreads();

    // reduce the 4 group-partials through smem (reuse)
    float* sbuf  = sm;                   // [4][1024]
    float* sbufS = sm + 4096;            // [4][32]
#pragma unroll
    for (int ii = 0; ii < 4; ii++)
#pragma unroll
        for (int jj = 0; jj < 4; jj++)
            sbuf[g * 1024 + (d0 + ii) * 32 + e0 + jj] = acc[ii][jj];
    if (te == 0) {
        sbufS[g * 32 + d0 + 0] = sa0; sbufS[g * 32 + d0 + 1] = sa1;
        sbufS[g * 32 + d0 + 2] = sa2; sbufS[g * 32 + d0 + 3] = sa3;
    }
    __syncthreads();

    const size_t pbase = ((size_t)bh * 32 + chunk) * 1056;
    for (int idx = tid; idx < 1024; idx += 256)
        g_part[pbase + idx] = sbuf[idx] + sbuf[1024 + idx] + sbuf[2048 + idx] + sbuf[3072 + idx];
    if (tid < 32)
        g_part[pbase + 1024 + tid] = sbufS[tid] + sbufS[32 + tid] + sbufS[64 + tid] + sbufS[96 + tid];
}

// =============================================================================
// K2b: per b: reduce 32 chunk-partials, normalize by sumexp, build fused
//      W2[ch=h*32+d][c] = sum_e w_out[c][h*32+e] * ctx[h][d][e] / S[h][d]
// smem: ctxs 4096 | Ss 128 | ws2 128*132  = 84,480 B
// =============================================================================
__global__ __launch_bounds__(256, 1)
void k_ctx_fin(const float* __restrict__ w_out)
{
    extern __shared__ float sm[];
    float* ctxs = sm;            // [h][d][e]
    float* Ss   = sm + 4096;     // 1/sumexp per (h,d)
    float* ws2  = sm + 4224;     // [ch2][c] stride 132

    const int b = blockIdx.x;
    const int tid = threadIdx.x;

    for (int lin = tid; lin < 16384; lin += 256) {
        int c = lin >> 7, ch2 = lin & 127;
        ws2[ch2 * 132 + c] = w_out[c * NCH + ch2];
    }

    for (int h = 0; h < 4; h++) {
        const size_t pb = (size_t)(b * 4 + h) * 32 * 1056;
        for (int idx = tid; idx < 1024; idx += 256) {
            float s = 0.f;
#pragma unroll
            for (int ch = 0; ch < 32; ch++) s += g_part[pb + (size_t)ch * 1056 + idx];
            ctxs[h * 1024 + idx] = s;
        }
    }
    if (tid < 128) {
        int h = tid >> 5, d = tid & 31;
        const size_t pb = (size_t)(b * 4 + h) * 32 * 1056 + 1024;
        float s = 0.f;
#pragma unroll
        for (int ch = 0; ch < 32; ch++) s += g_part[pb + (size_t)ch * 1056 + d];
        Ss[tid] = 1.0f / s;
    }
    __syncthreads();

    for (int oidx = tid; oidx < 16384; oidx += 256) {
        int ch = oidx >> 7, c = oidx & 127;     // lanes: consecutive c (bank-clean)
        int h = ch >> 5, d = ch & 31;
        const float* cr = &ctxs[h * 1024 + d * 32];
        float acc = 0.f;
#pragma unroll
        for (int e = 0; e < 32; e++)
            acc = fmaf(ws2[(h * 32 + e) * 132 + c], cr[e], acc);
        g_W2T[(size_t)b * 16384 + ch * NCH + c] = acc * Ss[ch];
    }
}

// =============================================================================
// K3: y = W2_b @ q + b_out, then LayerNorm over C.  128 positions / block.
// smem: qs[128][128] | W2s[128][68] | yb[128][132] | mean/rstd = 168,960 B
// =============================================================================
__global__ __launch_bounds__(256, 1)
void k_out(const float* __restrict__ b_out, const float* __restrict__ ln_g,
           const float* __restrict__ ln_b, float* __restrict__ out)
{
    extern __shared__ float sm[];
    float* qs     = sm;            // [ch][p] stride 128
    float* W2s    = sm + 16384;    // [ch][c] stride 68
    float* yb     = W2s + 8704;    // [c][p]  stride 132
    float* mean_s = yb + 16896;    // [128]
    float* rstd_s = mean_s + 128;  // [128]

    const int b   = blockIdx.x >> 7;
    const int n0  = (blockIdx.x & 127) << 7;
    const int tid = threadIdx.x;

    const float* qg = g_q + (size_t)b * NCH * NPOS + n0;
#pragma unroll
    for (int i = 0; i < 16; i++) {
        int lin = tid + i * 256;
        int ch = lin >> 5, pv = lin & 31;
        ((float4*)qs)[ch * 32 + pv] = ((const float4*)(qg + (size_t)ch * NPOS))[pv];
    }

    const int to = tid >> 4, tp = tid & 15;
    const int cl0 = to * 4, p0 = tp * 8;

    for (int half = 0; half < 2; half++) {
        __syncthreads();   // half0: covers qs fill; half1: prior GEMM done before W2s overwrite
#pragma unroll
        for (int i = 0; i < 32; i++) {
            int lin = tid + i * 256;          // 8192
            int ch = lin >> 6, cl = lin & 63;
            W2s[ch * 68 + cl] = g_W2T[(size_t)b * 16384 + ch * NCH + half * 64 + cl];
        }
        __syncthreads();

        float acc[4][8];
#pragma unroll
        for (int i = 0; i < 4; i++)
#pragma unroll
            for (int j = 0; j < 8; j++) acc[i][j] = 0.f;

#pragma unroll 4
        for (int ch = 0; ch < 128; ch++) {
            const float4 wv = *(const float4*)&W2s[ch * 68 + cl0];
            const float4 a0 = *(const float4*)&qs[ch * 128 + p0];
            const float4 a1 = *(const float4*)&qs[ch * 128 + p0 + 4];
            const float w4[4] = {wv.x, wv.y, wv.z, wv.w};
            const float xv[8] = {a0.x, a0.y, a0.z, a0.w, a1.x, a1.y, a1.z, a1.w};
#pragma unroll
            for (int i = 0; i < 4; i++)
#pragma unroll
                for (int j = 0; j < 8; j++)
                    acc[i][j] = fmaf(w4[i], xv[j], acc[i][j]);
        }

        const int cg = half * 64 + cl0;
#pragma unroll
        for (int i = 0; i < 4; i++) {
            const float bo = b_out[cg + i];
            float* r = &yb[(cg + i) * 132 + p0];
            *(float4*)(r)     = make_float4(acc[i][0] + bo, acc[i][1] + bo, acc[i][2] + bo, acc[i][3] + bo);
            *(float4*)(r + 4) = make_float4(acc[i][4] + bo, acc[i][5] + bo, acc[i][6] + bo, acc[i][7] + bo);
        }
    }
    __syncthreads();

    if (tid < 128) {
        const int p = tid;
        float s = 0.f, s2 = 0.f;
#pragma unroll 8
        for (int c = 0; c < 128; c++) {
            float v = yb[c * 132 + p];
            s += v; s2 = fmaf(v, v, s2);
        }
        const float mu = s * (1.0f / 128.0f);
        const float var = s2 * (1.0f / 128.0f) - mu * mu;
        mean_s[p] = mu;
        rstd_s[p] = rsqrtf(var + 1e-5f);
    }
    __syncthreads();

    float* ob = out + (size_t)b * NCH * NPOS + n0;
    for (int lin = tid; lin < 16384; lin += 256) {
        int c = lin >> 7, p = lin & 127;
        ob[(size_t)c * NPOS + p] =
            (yb[c * 132 + p] - mean_s[p]) * rstd_s[p] * ln_g[c] + ln_b[c];
    }
}

// =============================================================================
extern "C" void kernel_launch(void* const* d_in, const int* in_sizes, int n_in,
                              void* d_out, int out_size)
{
    const float* x     = (const float*)d_in[0];
    const float* w_qkv = (const float*)d_in[1];
    const float* w_out = (const float*)d_in[2];
    const float* b_out = (const float*)d_in[3];
    const float* ln_g  = (const float*)d_in[4];
    const float* ln_b  = (const float*)d_in[5];
    float* out = (float*)d_out;

    cudaFuncSetAttribute(k_qkv,      cudaFuncAttributeMaxDynamicSharedMemorySize, 167936);
    cudaFuncSetAttribute(k_ctx_part, cudaFuncAttributeMaxDynamicSharedMemorySize, 147456);
    cudaFuncSetAttribute(k_ctx_fin,  cudaFuncAttributeMaxDynamicSharedMemorySize,  84480);
    cudaFuncSetAttribute(k_out,      cudaFuncAttributeMaxDynamicSharedMemorySize, 168960);

    k_qkv<<<2048, 256, 167936>>>(x, w_qkv);
    k_ctx_part<<<2048, 256, 147456>>>();
    k_ctx_fin<<<16, 256, 84480>>>(w_out);
    k_out<<<2048, 256, 168960>>>(b_out, ln_g, ln_b, out);
}

// round 2
// speedup vs baseline: 1.3578x; 1.3578x over previous
#include <cuda_runtime.h>
#include <math.h>

#define NPOS 16384          // H*W
#define NB   16             // batch
#define NCH  128            // C == hidden
#define NCHUNK 32           // context n-chunks (512 each)

// ---------------- device scratch (allocation-free rule: __device__ globals) ----
__device__ float g_q[NB * NCH * NPOS];           // softmaxed*scale q  [b][h*32+d][n]
__device__ float g_k[NB * NCH * NPOS];           // raw k             [b][h*32+d][n]
__device__ float g_v[NB * NCH * NPOS];           // raw v             [b][h*32+e][n]
__device__ float g_part[NB * 4 * NCHUNK * 1056]; // per (b,h,chunk): 1024 ctx + 32 sumexp
__device__ float g_W2T[NB * NCH * NCH];          // fused weight, [b][ch=h*32+d][c]

// =============================================================================
// K1: qkv = w_qkv @ x.  Per block: 128 positions x all 384 out-ch (3 chunks of
// 128).  8x8 register tile per thread (256 thr = 128x128 tile).
// smem: xs[128][128] | ws[128][132] | qb[128][132] = 200,704 B
// =============================================================================
__global__ __launch_bounds__(256, 1)
void k_qkv(const float* __restrict__ x, const float* __restrict__ w_qkv)
{
    extern __shared__ float sm[];
    float* xs = sm;               // [c][p]   stride 128
    float* ws = sm + 16384;       // [c][o]   stride 132 (padded)
    float* qb = ws + 16896;       // [ch][p]  stride 132 (padded)

    const int b   = blockIdx.x >> 7;
    const int n0  = (blockIdx.x & 127) << 7;
    const int tid = threadIdx.x;

    const float* xb = x + (size_t)b * NCH * NPOS + n0;

    // load x tile (coalesced float4)
#pragma unroll
    for (int i = 0; i < 16; i++) {
        int lin = tid + i * 256;          // 4096 float4
        int c = lin >> 5, pv = lin & 31;
        ((float4*)xs)[c * 32 + pv] = ((const float4*)(xb + (size_t)c * NPOS))[pv];
    }

    const int to = tid >> 4, tp = tid & 15;
    const int o0 = to * 8,   p0 = tp * 8;

    for (int chunk = 0; chunk < 3; chunk++) {
        __syncthreads();   // chunk0: xs fill done; later: previous GEMM read of ws done
        // load w chunk transposed: ws[c][o], o in [chunk*128, +128)
#pragma unroll
        for (int i = 0; i < 64; i++) {
            int lin = tid + i * 256;      // 16384
            int o = lin >> 7, c = lin & 127;
            ws[c * 132 + o] = w_qkv[(chunk * 128 + o) * NCH + c];
        }
        __syncthreads();

        float acc[8][8];
#pragma unroll
        for (int i = 0; i < 8; i++)
#pragma unroll
            for (int j = 0; j < 8; j++) acc[i][j] = 0.f;

#pragma unroll 2
        for (int c = 0; c < 128; c++) {
            const float4 w0 = *(const float4*)&ws[c * 132 + o0];
            const float4 w1 = *(const float4*)&ws[c * 132 + o0 + 4];
            const float4 a0 = *(const float4*)&xs[c * 128 + p0];
            const float4 a1 = *(const float4*)&xs[c * 128 + p0 + 4];
            const float wv[8] = {w0.x, w0.y, w0.z, w0.w, w1.x, w1.y, w1.z, w1.w};
            const float xv[8] = {a0.x, a0.y, a0.z, a0.w, a1.x, a1.y, a1.z, a1.w};
#pragma unroll
            for (int i = 0; i < 8; i++)
#pragma unroll
                for (int j = 0; j < 8; j++)
                    acc[i][j] = fmaf(wv[i], xv[j], acc[i][j]);
        }

        if (chunk == 0) {                 // q -> smem for softmax
#pragma unroll
            for (int i = 0; i < 8; i++) {
                float* r = &qb[(o0 + i) * 132 + p0];
                *(float4*)(r)     = make_float4(acc[i][0], acc[i][1], acc[i][2], acc[i][3]);
                *(float4*)(r + 4) = make_float4(acc[i][4], acc[i][5], acc[i][6], acc[i][7]);
            }
        } else {
            float* gdst = (chunk == 1) ? g_k : g_v;
            float* dst = gdst + ((size_t)b * NCH + o0) * NPOS + n0 + p0;
#pragma unroll
            for (int i = 0; i < 8; i++) {
                *(float4*)(dst + (size_t)i * NPOS)     = make_float4(acc[i][0], acc[i][1], acc[i][2], acc[i][3]);
                *(float4*)(dst + (size_t)i * NPOS + 4) = make_float4(acc[i][4], acc[i][5], acc[i][6], acc[i][7]);
            }
        }
    }
    __syncthreads();

    // q softmax over d (32) per (h, p), then * DIM_HEAD^-0.5
    const float scale = 0.17677669529663687f; // 32^-0.5
#pragma unroll
    for (int it = 0; it < 2; it++) {
        int item = tid + it * 256;        // 512 = 4 heads * 128 p
        int h = item >> 7, p = item & 127;
        float m = -1e30f;
#pragma unroll
        for (int d = 0; d < 32; d++) m = fmaxf(m, qb[(h * 32 + d) * 132 + p]);
        float s = 0.f;
#pragma unroll
        for (int d = 0; d < 32; d++) {
            float e = __expf(qb[(h * 32 + d) * 132 + p] - m);
            qb[(h * 32 + d) * 132 + p] = e;
            s += e;
        }
        const float inv = scale / s;
        float* dst = g_q + ((size_t)b * NCH + h * 32) * NPOS + n0 + p;
#pragma unroll
        for (int d = 0; d < 32; d++)
            dst[(size_t)d * NPOS] = qb[(h * 32 + d) * 132 + p] * inv;
    }
}

// =============================================================================
// K2a: per (b,h,chunk of 512 n): partial ctx[d][e] = sum exp(k[d,n]) v[e,n]
//      plus partial sumexp per d.  smem: ekT[512][36] | vT[512][36] = 147,456 B
// =============================================================================
__global__ __launch_bounds__(256, 1)
void k_ctx_part()
{
    extern __shared__ float sm[];
    float* ekT = sm;            // [nn][d] stride 36
    float* vT  = sm + 18432;

    const int chunk = blockIdx.x & 31;
    const int bh    = blockIdx.x >> 5;   // b*4 + h
    const int tid   = threadIdx.x;
    const size_t base = (size_t)bh * 32 * NPOS + (size_t)chunk * 512;

    for (int i = 0; i < 64; i++) {
        int lin = tid + i * 256;         // 16384 = 32 d x 512 nn
        int d = lin >> 9, nn = lin & 511;
        ekT[nn * 36 + d] = __expf(g_k[base + (size_t)d * NPOS + nn]);
        vT [nn * 36 + d] =        g_v[base + (size_t)d * NPOS + nn];
    }
    __syncthreads();

    const int g  = tid >> 6;             // 4 groups, each owns 128 nn
    const int t  = tid & 63;
    const int td = t >> 3, te = t & 7;
    const int d0 = td * 4, e0 = te * 4;

    float acc[4][4];
#pragma unroll
    for (int i = 0; i < 4; i++)
#pragma unroll
        for (int j = 0; j < 4; j++) acc[i][j] = 0.f;
    float sa0 = 0.f, sa1 = 0.f, sa2 = 0.f, sa3 = 0.f;

#pragma unroll 4
    for (int i = 0; i < 128; i++) {
        int nn = g * 128 + i;
        const float4 a  = *(const float4*)&ekT[nn * 36 + d0];
        const float4 bv = *(const float4*)&vT [nn * 36 + e0];
        const float av[4] = {a.x, a.y, a.z, a.w};
        const float bb[4] = {bv.x, bv.y, bv.z, bv.w};
#pragma unroll
        for (int ii = 0; ii < 4; ii++)
#pragma unroll
            for (int jj = 0; jj < 4; jj++)
                acc[ii][jj] = fmaf(av[ii], bb[jj], acc[ii][jj]);
        if (te == 0) { sa0 += a.x; sa1 += a.y; sa2 += a.z; sa3 += a.w; }
    }
    __syncthreads();

    // reduce the 4 group-partials through smem (reuse)
    float* sbuf  = sm;                   // [4][1024]
    float* sbufS = sm + 4096;            // [4][32]
#pragma unroll
    for (int ii = 0; ii < 4; ii++)
#pragma unroll
        for (int jj = 0; jj < 4; jj++)
            sbuf[g * 1024 + (d0 + ii) * 32 + e0 + jj] = acc[ii][jj];
    if (te == 0) {
        sbufS[g * 32 + d0 + 0] = sa0; sbufS[g * 32 + d0 + 1] = sa1;
        sbufS[g * 32 + d0 + 2] = sa2; sbufS[g * 32 + d0 + 3] = sa3;
    }
    __syncthreads();

    const size_t pbase = ((size_t)bh * 32 + chunk) * 1056;
    for (int idx = tid; idx < 1024; idx += 256)
        g_part[pbase + idx] = sbuf[idx] + sbuf[1024 + idx] + sbuf[2048 + idx] + sbuf[3072 + idx];
    if (tid < 32)
        g_part[pbase + 1024 + tid] = sbufS[tid] + sbufS[32 + tid] + sbufS[64 + tid] + sbufS[96 + tid];
}

// =============================================================================
// K2b: per b: reduce 32 chunk-partials, normalize by sumexp, build fused
//      W2[ch=h*32+d][c] = sum_e w_out[c][h*32+e] * ctx[h][d][e] / S[h][d]
// =============================================================================
__global__ __launch_bounds__(256, 1)
void k_ctx_fin(const float* __restrict__ w_out)
{
    extern __shared__ float sm[];
    float* ctxs = sm;            // [h][d][e]
    float* Ss   = sm + 4096;     // 1/sumexp per (h,d)
    float* ws2  = sm + 4224;     // [ch2][c] stride 132

    const int b = blockIdx.x;
    const int tid = threadIdx.x;

    for (int lin = tid; lin < 16384; lin += 256) {
        int c = lin >> 7, ch2 = lin & 127;
        ws2[ch2 * 132 + c] = w_out[c * NCH + ch2];
    }

    for (int h = 0; h < 4; h++) {
        const size_t pb = (size_t)(b * 4 + h) * 32 * 1056;
        for (int idx = tid; idx < 1024; idx += 256) {
            float s = 0.f;
#pragma unroll
            for (int ch = 0; ch < 32; ch++) s += g_part[pb + (size_t)ch * 1056 + idx];
            ctxs[h * 1024 + idx] = s;
        }
    }
    if (tid < 128) {
        int h = tid >> 5, d = tid & 31;
        const size_t pb = (size_t)(b * 4 + h) * 32 * 1056 + 1024;
        float s = 0.f;
#pragma unroll
        for (int ch = 0; ch < 32; ch++) s += g_part[pb + (size_t)ch * 1056 + d];
        Ss[tid] = 1.0f / s;
    }
    __syncthreads();

    for (int oidx = tid; oidx < 16384; oidx += 256) {
        int ch = oidx >> 7, c = oidx & 127;     // lanes: consecutive c (bank-clean)
        int h = ch >> 5, d = ch & 31;
        const float* cr = &ctxs[h * 1024 + d * 32];
        float acc = 0.f;
#pragma unroll
        for (int e = 0; e < 32; e++)
            acc = fmaf(ws2[(h * 32 + e) * 132 + c], cr[e], acc);
        g_W2T[(size_t)b * 16384 + ch * NCH + c] = acc * Ss[ch];
    }
}

// =============================================================================
// K3: y = W2_b @ q + b_out, then LayerNorm over C.  128 positions / block.
// 8x8 register tile; LN stats via register partial reduction (no y staging).
// smem: qs[128][128] | W2s[128][132] | red[2][2048] | mean/rstd = 150,528 B
// =============================================================================
__global__ __launch_bounds__(256, 1)
void k_out(const float* __restrict__ b_out, const float* __restrict__ ln_g,
           const float* __restrict__ ln_b, float* __restrict__ out)
{
    extern __shared__ float sm[];
    float* qs     = sm;            // [ch][p] stride 128
    float* W2s    = sm + 16384;    // [ch][c] stride 132
    float* red    = W2s + 16896;   // [2][16][128]
    float* mean_s = red + 4096;    // [128]
    float* rstd_s = mean_s + 128;  // [128]

    const int b   = blockIdx.x >> 7;
    const int n0  = (blockIdx.x & 127) << 7;
    const int tid = threadIdx.x;

    const float* qg = g_q + (size_t)b * NCH * NPOS + n0;
#pragma unroll
    for (int i = 0; i < 16; i++) {
        int lin = tid + i * 256;
        int ch = lin >> 5, pv = lin & 31;
        ((float4*)qs)[ch * 32 + pv] = ((const float4*)(qg + (size_t)ch * NPOS))[pv];
    }
    // load full fused weight [ch][c]
#pragma unroll
    for (int i = 0; i < 64; i++) {
        int lin = tid + i * 256;          // 16384
        int ch = lin >> 7, cl = lin & 127;
        W2s[ch * 132 + cl] = g_W2T[(size_t)b * 16384 + lin];
    }
    __syncthreads();

    const int to = tid >> 4, tp = tid & 15;
    const int c0 = to * 8, p0 = tp * 8;

    float acc[8][8];
#pragma unroll
    for (int i = 0; i < 8; i++)
#pragma unroll
        for (int j = 0; j < 8; j++) acc[i][j] = 0.f;

#pragma unroll 2
    for (int ch = 0; ch < 128; ch++) {
        const float4 w0 = *(const float4*)&W2s[ch * 132 + c0];
        const float4 w1 = *(const float4*)&W2s[ch * 132 + c0 + 4];
        const float4 a0 = *(const float4*)&qs[ch * 128 + p0];
        const float4 a1 = *(const float4*)&qs[ch * 128 + p0 + 4];
        const float wv[8] = {w0.x, w0.y, w0.z, w0.w, w1.x, w1.y, w1.z, w1.w};
        const float xv[8] = {a0.x, a0.y, a0.z, a0.w, a1.x, a1.y, a1.z, a1.w};
#pragma unroll
        for (int i = 0; i < 8; i++)
#pragma unroll
            for (int j = 0; j < 8; j++)
                acc[i][j] = fmaf(wv[i], xv[j], acc[i][j]);
    }

    // add bias, per-thread partial sums over the 8 local channels
#pragma unroll
    for (int i = 0; i < 8; i++) {
        const float bo = b_out[c0 + i];
#pragma unroll
        for (int j = 0; j < 8; j++) acc[i][j] += bo;
    }
#pragma unroll
    for (int j = 0; j < 8; j++) {
        float s = 0.f, s2 = 0.f;
#pragma unroll
        for (int i = 0; i < 8; i++) {
            s += acc[i][j];
            s2 = fmaf(acc[i][j], acc[i][j], s2);
        }
        red[to * 128 + p0 + j]        = s;
        red[2048 + to * 128 + p0 + j] = s2;
    }
    __syncthreads();

    if (tid < 128) {
        const int p = tid;
        float s = 0.f, s2 = 0.f;
#pragma unroll
        for (int t = 0; t < 16; t++) {
            s  += red[t * 128 + p];
            s2 += red[2048 + t * 128 + p];
        }
        const float mu  = s * (1.0f / 128.0f);
        const float var = s2 * (1.0f / 128.0f) - mu * mu;
        mean_s[p] = mu;
        rstd_s[p] = rsqrtf(var + 1e-5f);
    }
    __syncthreads();

    float mu[8], rs[8];
#pragma unroll
    for (int j = 0; j < 8; j++) { mu[j] = mean_s[p0 + j]; rs[j] = rstd_s[p0 + j]; }

    float* ob = out + ((size_t)b * NCH + c0) * NPOS + n0 + p0;
#pragma unroll
    for (int i = 0; i < 8; i++) {
        const float gg = ln_g[c0 + i], bb = ln_b[c0 + i];
        float v[8];
#pragma unroll
        for (int j = 0; j < 8; j++)
            v[j] = (acc[i][j] - mu[j]) * rs[j] * gg + bb;
        *(float4*)(ob + (size_t)i * NPOS)     = make_float4(v[0], v[1], v[2], v[3]);
        *(float4*)(ob + (size_t)i * NPOS + 4) = make_float4(v[4], v[5], v[6], v[7]);
    }
}

// =============================================================================
extern "C" void kernel_launch(void* const* d_in, const int* in_sizes, int n_in,
                              void* d_out, int out_size)
{
    const float* x     = (const float*)d_in[0];
    const float* w_qkv = (const float*)d_in[1];
    const float* w_out = (const float*)d_in[2];
    const float* b_out = (const float*)d_in[3];
    const float* ln_g  = (const float*)d_in[4];
    const float* ln_b  = (const float*)d_in[5];
    float* out = (float*)d_out;

    cudaFuncSetAttribute(k_qkv,      cudaFuncAttributeMaxDynamicSharedMemorySize, 200704);
    cudaFuncSetAttribute(k_ctx_part, cudaFuncAttributeMaxDynamicSharedMemorySize, 147456);
    cudaFuncSetAttribute(k_ctx_fin,  cudaFuncAttributeMaxDynamicSharedMemorySize,  84480);
    cudaFuncSetAttribute(k_out,      cudaFuncAttributeMaxDynamicSharedMemorySize, 150528);

    k_qkv<<<2048, 256, 200704>>>(x, w_qkv);
    k_ctx_part<<<2048, 256, 147456>>>();
    k_ctx_fin<<<16, 256, 84480>>>(w_out);
    k_out<<<2048, 256, 150528>>>(b_out, ln_g, ln_b, out);
}